// round 9
// baseline (speedup 1.0000x reference)
#include <cuda_runtime.h>
#include <cuda_bf16.h>
#include <cstdint>

#define B 384
#define D 128
#define TS 32                    // Gram tile size
#define GT (B / TS)              // 12 tiles per dim
#define NPROD ((GT * (GT + 1)) / 2)   // 78 upper-triangle tiles
#define NBLK 128                 // total blocks (all consumers)
#define THREADS 256
#define PITCH4 33                // float4 pitch (+1 pad)
#define NA 3                     // anchors per consumer block
#define MARGIN 0.5f

__device__ float g_G[B * B];          // full Gram (mirrored on write)
__device__ float g_nrm[B];
__device__ float g_psum[NBLK];
__device__ float g_pcnt[NBLK];
__device__ unsigned int g_done;       // producer counter (zero-init)
__device__ unsigned int g_ticket;     // consumer ticket (zero-init)

__device__ __forceinline__ void cp_async16(uint32_t dst, const void* src) {
    asm volatile("cp.async.cg.shared.global [%0], [%1], 16;" :: "r"(dst), "l"(src));
}

__global__ __launch_bounds__(THREADS) void triplet_fused_kernel(
    const float* __restrict__ emb,
    const int* __restrict__ labels,
    float* __restrict__ out)
{
    __shared__ float4 sA[TS * PITCH4];
    __shared__ float4 sB[TS * PITCH4];
    __shared__ float  snrm[B];
    __shared__ int    slab[B];
    __shared__ float  dpos[NA][B];
    __shared__ int    npos[NA];
    __shared__ float  rsum[THREADS / 32];
    __shared__ float  rcnt[THREADS / 32];
    __shared__ int    is_last;

    const int tid = threadIdx.x;
    const int bid = blockIdx.x;

    // ============ PHASE 1: symmetric Gram tiles (blocks 0..77) ============
    if (bid < NPROD) {
        // map bid -> (ty, tx) with ty <= tx
        int p = bid, ty = 0;
        while (p >= GT - ty) { p -= GT - ty; ty++; }
        const int tx = ty + p;

        const float4* g4 = (const float4*)emb;
        const uint32_t sA_u = (uint32_t)__cvta_generic_to_shared(sA);
        const uint32_t sB_u = (uint32_t)__cvta_generic_to_shared(sB);

        #pragma unroll
        for (int it = 0; it < (TS * (D / 4)) / THREADS; it++) {  // 4
            int g = tid + THREADS * it;
            int r = g >> 5, c = g & 31;
            uint32_t soff = (uint32_t)((r * PITCH4 + c) * 16);
            cp_async16(sA_u + soff, g4 + (ty * TS + r) * (D / 4) + c);
            cp_async16(sB_u + soff, g4 + (tx * TS + r) * (D / 4) + c);
        }
        asm volatile("cp.async.commit_group;" ::: "memory");
        asm volatile("cp.async.wait_group 0;" ::: "memory");
        __syncthreads();

        // diagonal blocks emit norms (deterministic shfl tree)
        if (ty == tx) {
            const int r = tid >> 3;
            const int q = tid & 7;
            const float4* row = sA + r * PITCH4;
            float pp = 0.f;
            #pragma unroll
            for (int c = 0; c < 4; c++) {
                float4 x = row[q * 4 + c];
                pp = fmaf(x.x, x.x, fmaf(x.y, x.y, fmaf(x.z, x.z, fmaf(x.w, x.w, pp))));
            }
            pp += __shfl_down_sync(0xFFFFFFFFu, pp, 4, 8);
            pp += __shfl_down_sync(0xFFFFFFFFu, pp, 2, 8);
            pp += __shfl_down_sync(0xFFFFFFFFu, pp, 1, 8);
            if (q == 0) g_nrm[ty * TS + r] = pp;
        }

        const int i  = tid & 31;
        const int jg = tid >> 5;
        float a0 = 0.f, a1 = 0.f, a2 = 0.f, a3 = 0.f;
        const float4* arow = sA + i * PITCH4;
        const float4* b0 = sB + (jg * 4 + 0) * PITCH4;
        const float4* b1 = sB + (jg * 4 + 1) * PITCH4;
        const float4* b2 = sB + (jg * 4 + 2) * PITCH4;
        const float4* b3 = sB + (jg * 4 + 3) * PITCH4;

        #pragma unroll 8
        for (int k = 0; k < D / 4; k++) {
            float4 x = arow[k];
            float4 q = b0[k];
            a0 = fmaf(x.x, q.x, fmaf(x.y, q.y, fmaf(x.z, q.z, fmaf(x.w, q.w, a0))));
            q = b1[k];
            a1 = fmaf(x.x, q.x, fmaf(x.y, q.y, fmaf(x.z, q.z, fmaf(x.w, q.w, a1))));
            q = b2[k];
            a2 = fmaf(x.x, q.x, fmaf(x.y, q.y, fmaf(x.z, q.z, fmaf(x.w, q.w, a2))));
            q = b3[k];
            a3 = fmaf(x.x, q.x, fmaf(x.y, q.y, fmaf(x.z, q.z, fmaf(x.w, q.w, a3))));
        }

        const int gy = ty * TS + i;
        const int gx = tx * TS + jg * 4;
        *(float4*)&g_G[gy * B + gx] = make_float4(a0, a1, a2, a3);
        if (ty != tx) {    // mirror (column-coalesced within warp)
            g_G[(gx + 0) * B + gy] = a0;
            g_G[(gx + 1) * B + gy] = a1;
            g_G[(gx + 2) * B + gy] = a2;
            g_G[(gx + 3) * B + gy] = a3;
        }
        __threadfence();
        __syncthreads();
        if (tid == 0) atomicAdd(&g_done, 1u);
    }

    // ============ SYNC: wait for all 78 producer tiles ============
    if (tid == 0) {
        volatile unsigned int* vd = &g_done;
        while (*vd < NPROD) { __nanosleep(64); }
    }
    __syncthreads();
    __threadfence();   // acquire

    // ============ PHASE 2: triplet sums for anchors [3*bid, 3*bid+3) ========
    const int ab = bid * NA;

    for (int j = tid; j < B; j += THREADS) {
        snrm[j] = g_nrm[j];
        slab[j] = labels[j];
    }
    if (tid < NA) npos[tid] = 0;
    __syncthreads();

    int   lj[2];
    float dist[NA][2];
    #pragma unroll
    for (int u = 0; u < 2; u++) {
        int j = tid + THREADS * u;
        if (j < B) {
            lj[u] = slab[j];
            #pragma unroll
            for (int aa = 0; aa < NA; aa++) {
                const int a = ab + aa;
                float Gaj = __ldcg(&g_G[a * B + j]);
                float d = fmaxf(snrm[a] - 2.f * Gaj + snrm[j], 0.f);
                dist[aa][u] = d;
                if (lj[u] == slab[a] && j != a) {
                    int idx = atomicAdd(&npos[aa], 1);
                    dpos[aa][idx] = d;
                }
            }
        }
    }
    __syncthreads();

    float sum = 0.f, cnt = 0.f;
    #pragma unroll
    for (int u = 0; u < 2; u++) {
        int j = tid + THREADS * u;
        if (j < B) {
            #pragma unroll
            for (int aa = 0; aa < NA; aa++) {
                if (lj[u] != slab[ab + aa]) {
                    const float dn = dist[aa][u];
                    const int np = npos[aa];
                    for (int p = 0; p < np; p++) {
                        float v = dpos[aa][p] - dn + MARGIN;
                        if (v > 1e-16f) { sum += v; cnt += 1.f; }
                    }
                }
            }
        }
    }

    // block reduction (8 warps)
    const int lane = tid & 31;
    const int warp = tid >> 5;
    #pragma unroll
    for (int off = 16; off > 0; off >>= 1) {
        sum += __shfl_down_sync(0xFFFFFFFFu, sum, off);
        cnt += __shfl_down_sync(0xFFFFFFFFu, cnt, off);
    }
    if (lane == 0) { rsum[warp] = sum; rcnt[warp] = cnt; }
    __syncthreads();
    if (warp == 0) {
        float s = (lane < THREADS / 32) ? rsum[lane] : 0.f;
        float c = (lane < THREADS / 32) ? rcnt[lane] : 0.f;
        #pragma unroll
        for (int off = 16; off > 0; off >>= 1) {
            s += __shfl_down_sync(0xFFFFFFFFu, s, off);
            c += __shfl_down_sync(0xFFFFFFFFu, c, off);
        }
        if (lane == 0) {
            g_psum[bid] = s;
            g_pcnt[bid] = c;
        }
    }

    // last-block final reduction + counter resets (safe: all blocks have
    // passed the spin before the last ticket can be taken)
    __threadfence();
    if (tid == 0) {
        unsigned int tk = atomicAdd(&g_ticket, 1u);
        is_last = (tk == NBLK - 1);
    }
    __syncthreads();

    if (is_last && warp == 0) {
        __threadfence();
        volatile float* vs = g_psum;
        volatile float* vc = g_pcnt;
        double s = 0.0, c = 0.0;
        #pragma unroll
        for (int i = lane; i < NBLK; i += 32) {
            s += (double)vs[i];
            c += (double)vc[i];
        }
        #pragma unroll
        for (int off = 16; off > 0; off >>= 1) {
            s += __shfl_down_sync(0xFFFFFFFFu, s, off);
            c += __shfl_down_sync(0xFFFFFFFFu, c, off);
        }
        if (lane == 0) {
            out[0] = (float)(s / (c + 1e-16));
            g_ticket = 0;
            g_done   = 0;
        }
    }
}

extern "C" void kernel_launch(void* const* d_in, const int* in_sizes, int n_in,
                              void* d_out, int out_size) {
    const float* emb    = (const float*)d_in[0];
    const int*   labels = (const int*)d_in[1];
    float*       out    = (float*)d_out;

    triplet_fused_kernel<<<NBLK, THREADS>>>(emb, labels, out);
}

// round 11
// speedup vs baseline: 1.1502x; 1.1502x over previous
#include <cuda_runtime.h>
#include <cuda_bf16.h>
#include <cstdint>

#define B 384
#define D 128
#define TS 32                   // Gram tile size
#define GT (B / TS)             // 12 tiles per dim
#define NBLK1 (GT * GT)         // 144 gram blocks (single wave)
#define THR1 256
#define PITCH4 33               // float4 pitch (+1 pad) -> conflict-free
#define NA 3
#define NB (B / NA)             // 128 triplet blocks
#define THR2 384
#define NWARP2 (THR2 / 32)      // 12
#define MARGIN 0.5f

__device__ float g_G[B * B];          // Gram matrix scratch
__device__ float g_psum[NB];
__device__ float g_pcnt[NB];
__device__ unsigned int g_ticket;     // zero-init; reset by last block

__device__ __forceinline__ void cp_async16(uint32_t dst, const void* src) {
    asm volatile("cp.async.cg.shared.global [%0], [%1], 16;" :: "r"(dst), "l"(src));
}

// packed dual fp32 FMA: d.lo = fma(a.lo,b.lo,c.lo), d.hi = fma(a.hi,b.hi,c.hi)
__device__ __forceinline__ unsigned long long fma2(
    unsigned long long a, unsigned long long b, unsigned long long c) {
    unsigned long long d;
    asm("fma.rn.f32x2 %0, %1, %2, %3;" : "=l"(d) : "l"(a), "l"(b), "l"(c));
    return d;
}

__device__ __forceinline__ float hadd2(unsigned long long v) {
    return __uint_as_float((unsigned int)(v & 0xffffffffull)) +
           __uint_as_float((unsigned int)(v >> 32));
}

// ======================= Kernel 1: G = E * E^T (tiled, f32x2) ================
__global__ __launch_bounds__(THR1) void gram_kernel(const float* __restrict__ emb)
{
    __shared__ float4 sA[TS * PITCH4];
    __shared__ float4 sB[TS * PITCH4];

    const int tid = threadIdx.x;
    const int ty  = blockIdx.x / GT;
    const int tx  = blockIdx.x % GT;

    const float4* g4 = (const float4*)emb;         // B x 32 float4
    const uint32_t sA_u = (uint32_t)__cvta_generic_to_shared(sA);
    const uint32_t sB_u = (uint32_t)__cvta_generic_to_shared(sB);

    #pragma unroll
    for (int it = 0; it < (TS * (D / 4)) / THR1; it++) {    // 4 iters
        int g = tid + THR1 * it;                    // 0..1023
        int r = g >> 5, c = g & 31;
        uint32_t soff = (uint32_t)((r * PITCH4 + c) * 16);
        cp_async16(sA_u + soff, g4 + (ty * TS + r) * (D / 4) + c);
        cp_async16(sB_u + soff, g4 + (tx * TS + r) * (D / 4) + c);
    }
    asm volatile("cp.async.commit_group;" ::: "memory");
    asm volatile("cp.async.wait_group 0;" ::: "memory");
    __syncthreads();

    // 32x32 output tile: thread -> row i, 4 cols at jg*4; f32x2 accumulation
    const int i  = tid & 31;
    const int jg = tid >> 5;
    unsigned long long acc0 = 0ull, acc1 = 0ull, acc2 = 0ull, acc3 = 0ull;
    const ulonglong2* arow = (const ulonglong2*)(sA + i * PITCH4);
    const ulonglong2* b0 = (const ulonglong2*)(sB + (jg * 4 + 0) * PITCH4);
    const ulonglong2* b1 = (const ulonglong2*)(sB + (jg * 4 + 1) * PITCH4);
    const ulonglong2* b2 = (const ulonglong2*)(sB + (jg * 4 + 2) * PITCH4);
    const ulonglong2* b3 = (const ulonglong2*)(sB + (jg * 4 + 3) * PITCH4);

    #pragma unroll 8
    for (int k = 0; k < D / 4; k++) {
        ulonglong2 xa = arow[k];
        ulonglong2 xb = b0[k];                      // warp-uniform -> broadcast
        acc0 = fma2(xa.x, xb.x, acc0);
        acc0 = fma2(xa.y, xb.y, acc0);
        xb = b1[k];
        acc1 = fma2(xa.x, xb.x, acc1);
        acc1 = fma2(xa.y, xb.y, acc1);
        xb = b2[k];
        acc2 = fma2(xa.x, xb.x, acc2);
        acc2 = fma2(xa.y, xb.y, acc2);
        xb = b3[k];
        acc3 = fma2(xa.x, xb.x, acc3);
        acc3 = fma2(xa.y, xb.y, acc3);
    }

    *(float4*)&g_G[(ty * TS + i) * B + tx * TS + jg * 4] =
        make_float4(hadd2(acc0), hadd2(acc1), hadd2(acc2), hadd2(acc3));
}

// ================= Kernel 2: triplet reduction from G ========================
__global__ __launch_bounds__(THR2) void triplet_kernel(
    const int* __restrict__ labels,
    float* __restrict__ out)
{
    __shared__ float snrm[B];
    __shared__ int   slab[B];
    __shared__ float dpos[NA][B];
    __shared__ int   npos[NA];
    __shared__ float rsum[NWARP2];
    __shared__ float rcnt[NWARP2];
    __shared__ int   is_last;

    const int t  = threadIdx.x;      // == column j
    const int ab = blockIdx.x * NA;

    snrm[t] = __ldcg(&g_G[t * (B + 1)]);     // diag of G = squared norm
    slab[t] = labels[t];
    if (t < NA) npos[t] = 0;
    __syncthreads();

    const int lt = slab[t];
    float dist[NA];
    #pragma unroll
    for (int aa = 0; aa < NA; aa++) {
        const int a = ab + aa;
        float Gaj = __ldcg(&g_G[a * B + t]);          // coalesced row read
        dist[aa] = fmaxf(snrm[a] - 2.f * Gaj + snrm[t], 0.f);
        if (lt == slab[a] && t != a) {
            int idx = atomicAdd(&npos[aa], 1);
            dpos[aa][idx] = dist[aa];
        }
    }
    __syncthreads();

    float sum = 0.f, cnt = 0.f;
    #pragma unroll
    for (int aa = 0; aa < NA; aa++) {
        if (lt != slab[ab + aa]) {
            const float dn = dist[aa];
            const int np = npos[aa];
            for (int p = 0; p < np; p++) {
                float v = dpos[aa][p] - dn + MARGIN;
                if (v > 1e-16f) { sum += v; cnt += 1.f; }
            }
        }
    }

    // block reduction (12 warps)
    const int lane = t & 31;
    const int warp = t >> 5;
    #pragma unroll
    for (int off = 16; off > 0; off >>= 1) {
        sum += __shfl_down_sync(0xFFFFFFFFu, sum, off);
        cnt += __shfl_down_sync(0xFFFFFFFFu, cnt, off);
    }
    if (lane == 0) { rsum[warp] = sum; rcnt[warp] = cnt; }
    __syncthreads();
    if (warp == 0) {
        float s = (lane < NWARP2) ? rsum[lane] : 0.f;
        float c = (lane < NWARP2) ? rcnt[lane] : 0.f;
        #pragma unroll
        for (int off = 16; off > 0; off >>= 1) {
            s += __shfl_down_sync(0xFFFFFFFFu, s, off);
            c += __shfl_down_sync(0xFFFFFFFFu, c, off);
        }
        if (lane == 0) {
            g_psum[blockIdx.x] = s;
            g_pcnt[blockIdx.x] = c;
        }
    }

    // last-block final reduction
    __threadfence();
    if (t == 0) {
        unsigned int tk = atomicAdd(&g_ticket, 1u);
        is_last = (tk == NB - 1);
    }
    __syncthreads();

    if (is_last && warp == 0) {
        __threadfence();
        volatile float* vs = g_psum;
        volatile float* vc = g_pcnt;
        double s = 0.0, c = 0.0;
        #pragma unroll
        for (int i = lane; i < NB; i += 32) {
            s += (double)vs[i];
            c += (double)vc[i];
        }
        #pragma unroll
        for (int off = 16; off > 0; off >>= 1) {
            s += __shfl_down_sync(0xFFFFFFFFu, s, off);
            c += __shfl_down_sync(0xFFFFFFFFu, c, off);
        }
        if (lane == 0) {
            out[0] = (float)(s / (c + 1e-16));
            g_ticket = 0;                  // reset for graph replay
        }
    }
}

extern "C" void kernel_launch(void* const* d_in, const int* in_sizes, int n_in,
                              void* d_out, int out_size) {
    const float* emb    = (const float*)d_in[0];
    const int*   labels = (const int*)d_in[1];
    float*       out    = (float*)d_out;

    gram_kernel<<<NBLK1, THR1>>>(emb);
    triplet_kernel<<<NB, THR2>>>(labels, out);
}

// round 12
// speedup vs baseline: 1.2130x; 1.0545x over previous
#include <cuda_runtime.h>
#include <cuda_bf16.h>
#include <cstdint>

#define B 384
#define D 128
#define TS 32                   // Gram tile size
#define GT (B / TS)             // 12 tiles per dim
#define NBLK1 (GT * GT)         // 144 gram blocks (single wave)
#define THR1 256
#define PITCH4 33               // float4 pitch (+1 pad) -> conflict-free
#define NA 3
#define NB (B / NA)             // 128 triplet blocks
#define THR2 384
#define NWARP2 (THR2 / 32)      // 12
#define MARGIN 0.5f

__device__ float g_G[B * B];          // Gram matrix scratch
__device__ float g_psum[NB];
__device__ float g_pcnt[NB];
__device__ unsigned int g_ticket;     // zero-init; reset by last block

__device__ __forceinline__ void cp_async16(uint32_t dst, const void* src) {
    asm volatile("cp.async.cg.shared.global [%0], [%1], 16;" :: "r"(dst), "l"(src));
}

// ======================= Kernel 1: G = E * E^T (tiled) =======================
__global__ __launch_bounds__(THR1) void gram_kernel(const float* __restrict__ emb)
{
    __shared__ float4 sA[TS * PITCH4];
    __shared__ float4 sB[TS * PITCH4];

    const int tid = threadIdx.x;
    const int ty  = blockIdx.x / GT;
    const int tx  = blockIdx.x % GT;

    const float4* g4 = (const float4*)emb;         // B x 32 float4
    const uint32_t sA_u = (uint32_t)__cvta_generic_to_shared(sA);
    const uint32_t sB_u = (uint32_t)__cvta_generic_to_shared(sB);

    #pragma unroll
    for (int it = 0; it < (TS * (D / 4)) / THR1; it++) {    // 4 iters
        int g = tid + THR1 * it;                    // 0..1023
        int r = g >> 5, c = g & 31;
        uint32_t soff = (uint32_t)((r * PITCH4 + c) * 16);
        cp_async16(sA_u + soff, g4 + (ty * TS + r) * (D / 4) + c);
        cp_async16(sB_u + soff, g4 + (tx * TS + r) * (D / 4) + c);
    }
    asm volatile("cp.async.commit_group;" ::: "memory");
    asm volatile("cp.async.wait_group 0;" ::: "memory");
    __syncthreads();

    // 32x32 output tile: thread -> row i, 4 cols at jg*4
    const int i  = tid & 31;
    const int jg = tid >> 5;
    float a0 = 0.f, a1 = 0.f, a2 = 0.f, a3 = 0.f;
    const float4* arow = sA + i * PITCH4;
    const float4* b0 = sB + (jg * 4 + 0) * PITCH4;
    const float4* b1 = sB + (jg * 4 + 1) * PITCH4;
    const float4* b2 = sB + (jg * 4 + 2) * PITCH4;
    const float4* b3 = sB + (jg * 4 + 3) * PITCH4;

    #pragma unroll 8
    for (int k = 0; k < D / 4; k++) {
        float4 x = arow[k];
        float4 p = b0[k];   // warp-uniform -> broadcast
        a0 = fmaf(x.x, p.x, fmaf(x.y, p.y, fmaf(x.z, p.z, fmaf(x.w, p.w, a0))));
        p = b1[k];
        a1 = fmaf(x.x, p.x, fmaf(x.y, p.y, fmaf(x.z, p.z, fmaf(x.w, p.w, a1))));
        p = b2[k];
        a2 = fmaf(x.x, p.x, fmaf(x.y, p.y, fmaf(x.z, p.z, fmaf(x.w, p.w, a2))));
        p = b3[k];
        a3 = fmaf(x.x, p.x, fmaf(x.y, p.y, fmaf(x.z, p.z, fmaf(x.w, p.w, a3))));
    }

    *(float4*)&g_G[(ty * TS + i) * B + tx * TS + jg * 4] = make_float4(a0, a1, a2, a3);

    // release the dependent (PDL) launch as early as possible
    cudaTriggerProgrammaticLaunchCompletion();
}

// ================= Kernel 2: triplet reduction from G (PDL consumer) =========
__global__ __launch_bounds__(THR2) void triplet_kernel(
    const int* __restrict__ labels,
    float* __restrict__ out)
{
    __shared__ float snrm[B];
    __shared__ int   slab[B];
    __shared__ float dpos[NA][B];
    __shared__ int   npos[NA];
    __shared__ float rsum[NWARP2];
    __shared__ float rcnt[NWARP2];
    __shared__ int   is_last;

    const int t  = threadIdx.x;      // == column j
    const int ab = blockIdx.x * NA;

    // ---- G-independent prologue (overlaps with gram kernel) ----
    slab[t] = labels[t];
    if (t < NA) npos[t] = 0;

    // ---- wait for gram kernel completion (memory-visible) ----
    cudaGridDependencySynchronize();

    snrm[t] = __ldcg(&g_G[t * (B + 1)]);     // diag of G = squared norm
    __syncthreads();

    const int lt = slab[t];
    float dist[NA];
    #pragma unroll
    for (int aa = 0; aa < NA; aa++) {
        const int a = ab + aa;
        float Gaj = __ldcg(&g_G[a * B + t]);          // coalesced row read
        dist[aa] = fmaxf(snrm[a] - 2.f * Gaj + snrm[t], 0.f);
        if (lt == slab[a] && t != a) {
            int idx = atomicAdd(&npos[aa], 1);
            dpos[aa][idx] = dist[aa];
        }
    }
    __syncthreads();

    float sum = 0.f, cnt = 0.f;
    #pragma unroll
    for (int aa = 0; aa < NA; aa++) {
        if (lt != slab[ab + aa]) {
            const float dn = dist[aa];
            const int np = npos[aa];
            for (int p = 0; p < np; p++) {
                float v = dpos[aa][p] - dn + MARGIN;
                if (v > 1e-16f) { sum += v; cnt += 1.f; }
            }
        }
    }

    // block reduction (12 warps)
    const int lane = t & 31;
    const int warp = t >> 5;
    #pragma unroll
    for (int off = 16; off > 0; off >>= 1) {
        sum += __shfl_down_sync(0xFFFFFFFFu, sum, off);
        cnt += __shfl_down_sync(0xFFFFFFFFu, cnt, off);
    }
    if (lane == 0) { rsum[warp] = sum; rcnt[warp] = cnt; }
    __syncthreads();
    if (warp == 0) {
        float s = (lane < NWARP2) ? rsum[lane] : 0.f;
        float c = (lane < NWARP2) ? rcnt[lane] : 0.f;
        #pragma unroll
        for (int off = 16; off > 0; off >>= 1) {
            s += __shfl_down_sync(0xFFFFFFFFu, s, off);
            c += __shfl_down_sync(0xFFFFFFFFu, c, off);
        }
        if (lane == 0) {
            g_psum[blockIdx.x] = s;
            g_pcnt[blockIdx.x] = c;
        }
    }

    // last-block final reduction
    __threadfence();
    if (t == 0) {
        unsigned int tk = atomicAdd(&g_ticket, 1u);
        is_last = (tk == NB - 1);
    }
    __syncthreads();

    if (is_last && warp == 0) {
        __threadfence();
        volatile float* vs = g_psum;
        volatile float* vc = g_pcnt;
        double s = 0.0, c = 0.0;
        #pragma unroll
        for (int i = lane; i < NB; i += 32) {
            s += (double)vs[i];
            c += (double)vc[i];
        }
        #pragma unroll
        for (int off = 16; off > 0; off >>= 1) {
            s += __shfl_down_sync(0xFFFFFFFFu, s, off);
            c += __shfl_down_sync(0xFFFFFFFFu, c, off);
        }
        if (lane == 0) {
            out[0] = (float)(s / (c + 1e-16));
            g_ticket = 0;                  // reset for graph replay
        }
    }
}

extern "C" void kernel_launch(void* const* d_in, const int* in_sizes, int n_in,
                              void* d_out, int out_size) {
    const float* emb    = (const float*)d_in[0];
    const int*   labels = (const int*)d_in[1];
    float*       out    = (float*)d_out;

    gram_kernel<<<NBLK1, THR1>>>(emb);

    // PDL: triplet_kernel launches while gram_kernel runs; it self-synchronizes
    // via cudaGridDependencySynchronize() before touching g_G.
    cudaLaunchConfig_t cfg = {};
    cfg.gridDim  = dim3(NB, 1, 1);
    cfg.blockDim = dim3(THR2, 1, 1);
    cfg.dynamicSmemBytes = 0;
    cfg.stream = 0;   // legacy default stream (same one the harness captures)
    cudaLaunchAttribute attrs[1];
    attrs[0].id = cudaLaunchAttributeProgrammaticStreamSerialization;
    attrs[0].val.programmaticStreamSerializationAllowed = 1;
    cfg.attrs = attrs;
    cfg.numAttrs = 1;
    cudaLaunchKernelEx(&cfg, triplet_kernel, labels, out);
}